// round 6
// baseline (speedup 1.0000x reference)
#include <cuda_runtime.h>
#include <cstdint>

#define C_EPS     1e-12f
#define C_TOL     1e-6f
#define C_LAM     10000.0f
#define C_INVLAM  1e-4f

// Fully fused CBF-QP projection.
// Case 1: clip to unit ball if feasible.
// Case 2: soft halfspace projection if inside ball.
// Case 3: both constraints active -> root of
//   phi(t) = (p - tA) - (b + t/LAM)*||u - t a|| = 0
// Analytic start (quadratic from dropping t/LAM, or deep-infeasible asymptote),
// then 4 clamped Newton steps. Same unique root the reference's
// doubling+bisection+Newton converges to.
__global__ void __launch_bounds__(256) cbf_fused_kernel(
    const float* __restrict__ u_nom,   // [n,2]
    const float* __restrict__ obs,     // [n,6]
    float*       __restrict__ out,     // [n,2]
    int n)
{
    int i = blockIdx.x * 256 + threadIdx.x;
    if (i >= n) return;

    float2 u  = *reinterpret_cast<const float2*>(u_nom + 2 * i);
    const float* o = obs + 6 * i;
    float2 pr = *reinterpret_cast<const float2*>(o + 2);
    float2 vh = *reinterpret_cast<const float2*>(o + 4);

    float px = pr.x, py = pr.y;
    float h  = fmaf(px, px, py * py) - 1.0f;                      // SAFE_DIST^2 = 1
    float ax = -2.0f * px, ay = -2.0f * py;
    float b  = fmaf(2.0f, h, -2.0f * fmaf(px, vh.x, py * vh.y)); // ALPHA*h - 2 p.v

    float A = fmaf(ax, ax, ay * ay);
    float p = fmaf(ax, u.x, ay * u.y);
    float N = fmaf(u.x, u.x, u.y * u.y);

    // ---- Case 1: clip to unit ball, test feasibility ----
    float s1  = fminf(1.0f, rsqrtf(fmaxf(N, C_EPS)));   // min(1, U/||u||)
    float u1x = u.x * s1, u1y = u.y * s1;
    bool feas1 = fmaf(ax, u1x, ay * u1y) <= b + C_TOL;

    // ---- Case 2: soft halfspace projection, test ball ----
    float t2  = __fdividef(C_LAM * (p - b), fmaf(C_LAM, A, 1.0f));
    float u2x = fmaf(-t2, ax, u.x), u2y = fmaf(-t2, ay, u.y);
    bool ok2  = (t2 >= -C_TOL) && (fmaf(u2x, u2x, u2y * u2y) <= 1.0f + C_TOL);

    float ox = feas1 ? u1x : u2x;
    float oy = feas1 ? u1y : u2y;
    bool need3 = !(feas1 || ok2);

    // ---- Case 3 (predicated; skipped only if no lane needs it) ----
    if (__any_sync(__activemask(), need3)) {
        float Ac   = fmaxf(A, 1e-30f);
        float rsA  = rsqrtf(Ac);
        float sa   = Ac * rsA;                 // sqrt(A)
        float invA = rsA * rsA;                // 1/A

        // Quadratic start (valid when A - b^2 > 0):
        //   t_q = ( p - b*sqrt((A*N - p^2)/(A - b^2)) ) / A
        float s    = A - b * b;
        float cs2  = fmaxf(fmaf(A, N, -p * p), 0.0f);   // A*N - p^2 >= 0
        float rad  = sqrtf(fmaxf(__fdividef(cs2, s), 0.0f));
        float t_q  = fmaf(-b, rad, p) * invA;

        // Deep-infeasible start (b < 0, b^2 >= A): t ~ LAM*(-b - sqrt(A))
        float t_dp = C_LAM * (-b - sa);

        float t3 = (s > 0.0f) ? t_q : t_dp;

        // Provable upper bound on the root (keeps Newton safeguarded):
        //   b >= 0: root <= p/A ;  b < 0: root <= max(p/A, -LAM*b)
        float hb = p * invA;
        if (b < 0.0f) hb = fmaxf(hb, -C_LAM * b);
        t3 = fminf(fmaxf(t3, 0.0f), hb);

        // 4 clamped Newton steps on the exact phi.
        #pragma unroll
        for (int k = 0; k < 4; k++) {
            float nrm2 = fmaxf(fmaf(t3, fmaf(t3, A, -2.0f * p), N), C_EPS);
            float rnrm = rsqrtf(nrm2);
            float nrm  = nrm2 * rnrm;
            float R    = fmaf(t3, C_INVLAM, b);
            float L    = fmaf(-t3, A, p);
            float f    = fmaf(-R, nrm, L);
            // df = -A - nrm/LAM - R*(tA - p)/nrm ;  (tA - p) = -L
            float df   = fmaf(R * L, rnrm, fmaf(-C_INVLAM, nrm, -A));
            df = (fabsf(df) > 1e-8f) ? df : -1e-8f;
            t3 = t3 - __fdividef(f, df);
            t3 = fminf(fmaxf(t3, 0.0f), hb);
        }

        float nrm2 = fmaxf(fmaf(t3, fmaf(t3, A, -2.0f * p), N), C_EPS);
        float inv  = fminf(rsqrtf(nrm2), 1.0f);          // 1/max(||u-ta||,1)
        float u3x  = fmaf(-t3, ax, u.x) * inv;
        float u3y  = fmaf(-t3, ay, u.y) * inv;

        ox = need3 ? u3x : ox;
        oy = need3 ? u3y : oy;
    }

    *reinterpret_cast<float2*>(out + 2 * i) = make_float2(ox, oy);
}

extern "C" void kernel_launch(void* const* d_in, const int* in_sizes, int n_in,
                              void* d_out, int out_size) {
    const float* u_nom = (const float*)d_in[0];
    const float* obs   = (const float*)d_in[1];
    float* out = (float*)d_out;

    int n = in_sizes[0] / 2;
    int threads = 256;
    int blocks  = (n + threads - 1) / threads;
    cbf_fused_kernel<<<blocks, threads>>>(u_nom, obs, out, n);
}

// round 7
// speedup vs baseline: 1.0049x; 1.0049x over previous
#include <cuda_runtime.h>
#include <cstdint>

#define C_EPS     1e-12f
#define C_TOL     1e-6f
#define C_LAM     10000.0f
#define C_INVLAM  1e-4f

// One CBF-QP row, fully branchless.
__device__ __forceinline__ float2 solve_row(
    float ux, float uy, float px, float py, float vx, float vy)
{
    float h  = fmaf(px, px, py * py) - 1.0f;                     // SAFE_DIST^2 = 1
    float ax = -2.0f * px, ay = -2.0f * py;
    float b  = fmaf(2.0f, h, -2.0f * fmaf(px, vx, py * vy));     // ALPHA*h - 2 p.v

    float A = fmaf(ax, ax, ay * ay);
    float p = fmaf(ax, ux, ay * uy);
    float N = fmaf(ux, ux, uy * uy);

    // ---- Case 1: clip to unit ball, test feasibility ----
    float s1  = fminf(1.0f, rsqrtf(fmaxf(N, C_EPS)));
    float u1x = ux * s1, u1y = uy * s1;
    bool feas1 = fmaf(ax, u1x, ay * u1y) <= b + C_TOL;

    // ---- Case 2: soft halfspace projection, test ball ----
    float t2  = __fdividef(C_LAM * (p - b), fmaf(C_LAM, A, 1.0f));
    float u2x = fmaf(-t2, ax, ux), u2y = fmaf(-t2, ay, uy);
    bool ok2  = (t2 >= -C_TOL) && (fmaf(u2x, u2x, u2y * u2y) <= 1.0f + C_TOL);

    // ---- Case 3: analytic start + 6 clamped Newton steps on exact phi ----
    float Ac   = fmaxf(A, 1e-30f);
    float rsA  = rsqrtf(Ac);
    float sa   = Ac * rsA;                  // sqrt(A)
    float invA = rsA * rsA;                 // 1/A

    // Quadratic start (LAM -> inf limit), valid when s = A - b^2 > 0:
    //   t_q = ( p - b*sqrt((A*N - p^2)/(A - b^2)) ) / A
    float s    = A - b * b;
    float cs2  = fmaxf(fmaf(A, N, -p * p), 0.0f);     // A*N - p^2 >= 0 (Cauchy-Schwarz)
    float rad  = sqrtf(fmaxf(__fdividef(cs2, s), 0.0f));
    float t_q  = fmaf(-b, rad, p) * invA;
    // Deep-infeasible asymptote (b < 0, b^2 >= A): t ~ LAM*(-b - sqrt(A))
    float t_dp = C_LAM * (-b - sa);
    float t3   = (s > 0.0f) ? t_q : t_dp;

    // Safeguard bounds on the root.
    float hb = p * invA;
    if (b < 0.0f) hb = fmaxf(hb, -C_LAM * b);
    t3 = fminf(fmaxf(t3, 0.0f), hb);

    #pragma unroll
    for (int k = 0; k < 6; k++) {
        float nrm2 = fmaxf(fmaf(t3, fmaf(t3, A, -2.0f * p), N), C_EPS);
        float rnrm = rsqrtf(nrm2);
        float nrm  = nrm2 * rnrm;
        float R    = fmaf(t3, C_INVLAM, b);
        float L    = fmaf(-t3, A, p);
        float f    = fmaf(-R, nrm, L);
        // df = -A - nrm/LAM + R*L/nrm
        float df   = fmaf(R * L, rnrm, fmaf(-C_INVLAM, nrm, -A));
        df = (fabsf(df) > 1e-8f) ? df : -1e-8f;
        t3 = t3 - __fdividef(f, df);
        t3 = fminf(fmaxf(t3, 0.0f), hb);
    }

    float nrm2 = fmaxf(fmaf(t3, fmaf(t3, A, -2.0f * p), N), C_EPS);
    float inv  = fminf(rsqrtf(nrm2), 1.0f);            // 1/max(||u - t a||, 1)
    float u3x  = fmaf(-t3, ax, ux) * inv;
    float u3y  = fmaf(-t3, ay, uy) * inv;

    float ox = feas1 ? u1x : (ok2 ? u2x : u3x);
    float oy = feas1 ? u1y : (ok2 ? u2y : u3y);
    return make_float2(ox, oy);
}

// 2 rows per thread, float4 I/O (u: 1x128b, obs: 3x128b, out: 1x128b per pair).
__global__ void __launch_bounds__(256) cbf_fused2_kernel(
    const float4* __restrict__ u4,     // [n/2] pairs of u rows
    const float4* __restrict__ o4,     // [3*n/2] obs as float4
    float4*       __restrict__ out4,   // [n/2]
    int npair)
{
    int j = blockIdx.x * 256 + threadIdx.x;
    if (j >= npair) return;

    float4 u  = u4[j];
    float4 a0 = o4[3 * j + 0];   // row0: o0 o1 o2 o3
    float4 a1 = o4[3 * j + 1];   // row0: o4 o5 | row1: o0 o1
    float4 a2 = o4[3 * j + 2];   // row1: o2 o3 o4 o5

    float2 r0 = solve_row(u.x, u.y, a0.z, a0.w, a1.x, a1.y);
    float2 r1 = solve_row(u.z, u.w, a2.x, a2.y, a2.z, a2.w);

    out4[j] = make_float4(r0.x, r0.y, r1.x, r1.y);
}

// Scalar tail kernel for odd n (not hit for B = 4M, kept for generality).
__global__ void cbf_tail_kernel(
    const float* __restrict__ u_nom,
    const float* __restrict__ obs,
    float*       __restrict__ out,
    int i)
{
    const float* o = obs + 6 * i;
    float2 r = solve_row(u_nom[2 * i], u_nom[2 * i + 1],
                         o[2], o[3], o[4], o[5]);
    out[2 * i]     = r.x;
    out[2 * i + 1] = r.y;
}

extern "C" void kernel_launch(void* const* d_in, const int* in_sizes, int n_in,
                              void* d_out, int out_size) {
    const float* u_nom = (const float*)d_in[0];
    const float* obs   = (const float*)d_in[1];
    float* out = (float*)d_out;

    int n = in_sizes[0] / 2;
    int npair = n / 2;

    int threads = 256;
    int blocks  = (npair + threads - 1) / threads;
    cbf_fused2_kernel<<<blocks, threads>>>(
        (const float4*)u_nom, (const float4*)obs, (float4*)out, npair);

    if (n & 1)
        cbf_tail_kernel<<<1, 1>>>(u_nom, obs, out, n - 1);
}